// round 1
// baseline (speedup 1.0000x reference)
#include <cuda_runtime.h>
#include <math.h>

#define BT      4096
#define KK      64
#define DD      256
#define PP      4
#define KPP     16
#define ROWS    16
#define THREADS 256
#define COLS    1024   // P*D

// shared layout (floats):
// w_s[ROWS*KK]=1024 | winv_s[ROWS*PP]=64 | alpha_s[ROWS*PP]=64 | red_s[ROWS*8*2]=256
// pidx_s[64] (ints) | u_s[ROWS*COLS]=16384
#define SMEM_FLOATS (1024 + 64 + 64 + 256 + 64 + ROWS*COLS)

__global__ __launch_bounds__(THREADS, 2)
void fs_kernel(const float* __restrict__ E_S, const float* __restrict__ W,
               const int* __restrict__ part_idx,
               const float* __restrict__ part_W, const float* __restrict__ part_b,
               const float* __restrict__ v, const float* __restrict__ c,
               const float* __restrict__ ln_g, const float* __restrict__ ln_b,
               const float* __restrict__ proj_W, const float* __restrict__ proj_b,
               const float* __restrict__ out_g, const float* __restrict__ out_b,
               float* __restrict__ out)
{
    extern __shared__ float sm[];
    float* w_s     = sm;                      // [ROWS][KK]
    float* winv_s  = w_s + ROWS * KK;         // [ROWS][PP]
    float* alpha_s = winv_s + ROWS * PP;      // [ROWS][PP]
    float* red_s   = alpha_s + ROWS * PP;     // [ROWS][8][2]
    int*   pidx_s  = (int*)(red_s + ROWS * 16);
    float* u_s     = (float*)(pidx_s + 64);   // [ROWS][COLS]
    float4* u4_s   = (float4*)u_s;            // [ROWS][256]

    const int tid = threadIdx.x;
    const int bt0 = blockIdx.x * ROWS;

    // ---- load part_idx + W tile, compute per-(row,part) inverse weight sums ----
    if (tid < 64) pidx_s[tid] = part_idx[tid];
#pragma unroll
    for (int i = 0; i < (ROWS * KK) / THREADS; i++) {
        int idx = tid + i * THREADS;
        w_s[idx] = W[(size_t)bt0 * KK + idx];
    }
    __syncthreads();
    if (tid < ROWS * PP) {
        int r = tid >> 2, p = tid & 3;
        float s = 0.f;
#pragma unroll
        for (int kp = 0; kp < KPP; kp++) s += w_s[r * KK + pidx_s[p * KPP + kp]];
        winv_s[tid] = 1.0f / (s + 1e-6f);
    }
    __syncthreads();

    // ---- phase 1: weighted segment-sum u[r][p][d] (the big HBM stream) ----
    {
        const int p0 = tid >> 6;   // part
        const int d4 = tid & 63;   // float4 chunk of D
        int kidx[KPP];
#pragma unroll
        for (int kp = 0; kp < KPP; kp++) kidx[kp] = pidx_s[p0 * KPP + kp];

        for (int r = 0; r < ROWS; r++) {
            const float4* E4 = (const float4*)(E_S + (size_t)(bt0 + r) * KK * DD);
            const float inv = winv_s[r * PP + p0];
            float4 acc = make_float4(0.f, 0.f, 0.f, 0.f);
#pragma unroll
            for (int kp = 0; kp < KPP; kp++) {
                const int k = kidx[kp];
                const float wv = w_s[r * KK + k];
                const float4 e = E4[k * 64 + d4];
                acc.x = fmaf(wv, e.x, acc.x);
                acc.y = fmaf(wv, e.y, acc.y);
                acc.z = fmaf(wv, e.z, acc.z);
                acc.w = fmaf(wv, e.w, acc.w);
            }
            acc.x *= inv; acc.y *= inv; acc.z *= inv; acc.w *= inv;
            u4_s[r * 256 + p0 * 64 + d4] = acc;
        }
    }
    __syncthreads();

    // ---- phase 2a: per-part linear u_hat = u @ Wp^T + bp (overwrite u slice) ----
#pragma unroll 1
    for (int p = 0; p < PP; p++) {
        const float4* wp = (const float4*)(part_W + ((size_t)(p * DD + tid)) * DD);
        float acc[ROWS];
        const float b = part_b[p * DD + tid];
#pragma unroll
        for (int r = 0; r < ROWS; r++) acc[r] = b;

        for (int i4 = 0; i4 < DD / 4; i4++) {
            const float4 w4 = wp[i4];
#pragma unroll
            for (int r = 0; r < ROWS; r++) {
                const float4 u4 = u4_s[r * 256 + p * 64 + i4];
                acc[r] = fmaf(u4.x, w4.x,
                         fmaf(u4.y, w4.y,
                         fmaf(u4.z, w4.z,
                         fmaf(u4.w, w4.w, acc[r]))));
            }
        }
        __syncthreads();
#pragma unroll
        for (int r = 0; r < ROWS; r++) u_s[r * COLS + p * DD + tid] = acc[r];
        __syncthreads();
    }

    // ---- phase 2b: LN stats + sigmoid gate per (row, part); warp per pair ----
    {
        const int wid = tid >> 5, lane = tid & 31;
#pragma unroll 1
        for (int j = 0; j < (ROWS * PP) / 8; j++) {
            const int pair = wid * 8 + j;
            const int r = pair >> 2, p = pair & 3;
            float s1 = 0.f, s2 = 0.f, s3 = 0.f, s4 = 0.f, s5 = 0.f;
#pragma unroll
            for (int i = 0; i < DD / 32; i++) {
                const int col = lane + i * 32;
                const float x  = u_s[r * COLS + p * DD + col];
                const float vv = v[p * DD + col];
                const float gv = ln_g[p * DD + col] * vv;
                const float bv = ln_b[p * DD + col] * vv;
                s1 += x; s2 += x * x; s3 += x * gv; s4 += gv; s5 += bv;
            }
#pragma unroll
            for (int off = 16; off; off >>= 1) {
                s1 += __shfl_xor_sync(0xffffffffu, s1, off);
                s2 += __shfl_xor_sync(0xffffffffu, s2, off);
                s3 += __shfl_xor_sync(0xffffffffu, s3, off);
                s4 += __shfl_xor_sync(0xffffffffu, s4, off);
                s5 += __shfl_xor_sync(0xffffffffu, s5, off);
            }
            if (lane == 0) {
                const float m   = s1 * (1.0f / DD);
                const float var = s2 * (1.0f / DD) - m * m;
                const float rs  = rsqrtf(var + 1e-5f);
                const float dot = rs * (s3 - m * s4) + s5 + c[p];
                alpha_s[r * PP + p] = 1.0f / (1.0f + __expf(-dot));
            }
        }
    }
    __syncthreads();

    // ---- scale u_hat by alpha in place -> u_tilde (=Z) ----
#pragma unroll
    for (int p = 0; p < PP; p++) {
#pragma unroll
        for (int r = 0; r < ROWS; r++)
            u_s[r * COLS + p * DD + tid] *= alpha_s[r * PP + p];
    }
    __syncthreads();

    // ---- phase 2c: projection S = Z @ proj_W^T + proj_b ----
    float acc2[ROWS];
    {
        const float4* pw = (const float4*)(proj_W + (size_t)tid * COLS);
        const float pb = proj_b[tid];
#pragma unroll
        for (int r = 0; r < ROWS; r++) acc2[r] = pb;

        for (int j4 = 0; j4 < COLS / 4; j4++) {
            const float4 w4 = pw[j4];
#pragma unroll
            for (int r = 0; r < ROWS; r++) {
                const float4 u4 = u4_s[r * 256 + j4];
                acc2[r] = fmaf(u4.x, w4.x,
                          fmaf(u4.y, w4.y,
                          fmaf(u4.z, w4.z,
                          fmaf(u4.w, w4.w, acc2[r]))));
            }
        }
    }

    // ---- phase 2d: final LayerNorm across D (threads hold one column each) ----
    {
        const int wid = tid >> 5, lane = tid & 31;
#pragma unroll
        for (int r = 0; r < ROWS; r++) {
            float s1 = acc2[r];
            float s2 = acc2[r] * acc2[r];
#pragma unroll
            for (int off = 16; off; off >>= 1) {
                s1 += __shfl_xor_sync(0xffffffffu, s1, off);
                s2 += __shfl_xor_sync(0xffffffffu, s2, off);
            }
            if (lane == 0) {
                red_s[(r * 8 + wid) * 2 + 0] = s1;
                red_s[(r * 8 + wid) * 2 + 1] = s2;
            }
        }
        __syncthreads();
        const float og = out_g[tid], ob = out_b[tid];
#pragma unroll
        for (int r = 0; r < ROWS; r++) {
            float s1 = 0.f, s2 = 0.f;
#pragma unroll
            for (int w = 0; w < 8; w++) {
                s1 += red_s[(r * 8 + w) * 2 + 0];
                s2 += red_s[(r * 8 + w) * 2 + 1];
            }
            const float m   = s1 * (1.0f / DD);
            const float var = s2 * (1.0f / DD) - m * m;
            const float rs  = rsqrtf(var + 1e-5f);
            out[(size_t)(bt0 + r) * DD + tid] = (acc2[r] - m) * rs * og + ob;
        }
    }
}

extern "C" void kernel_launch(void* const* d_in, const int* in_sizes, int n_in,
                              void* d_out, int out_size)
{
    (void)in_sizes; (void)n_in; (void)out_size;
    const float* E_S    = (const float*)d_in[0];
    const float* W      = (const float*)d_in[1];
    const int*   pidx   = (const int*)  d_in[2];
    const float* part_W = (const float*)d_in[3];
    const float* part_b = (const float*)d_in[4];
    const float* v      = (const float*)d_in[5];
    const float* c      = (const float*)d_in[6];
    const float* ln_g   = (const float*)d_in[7];
    const float* ln_b   = (const float*)d_in[8];
    const float* proj_W = (const float*)d_in[9];
    const float* proj_b = (const float*)d_in[10];
    const float* out_g  = (const float*)d_in[11];
    const float* out_b  = (const float*)d_in[12];
    float* out = (float*)d_out;

    const int smem_bytes = SMEM_FLOATS * (int)sizeof(float);
    cudaFuncSetAttribute(fs_kernel, cudaFuncAttributeMaxDynamicSharedMemorySize, smem_bytes);
    fs_kernel<<<BT / ROWS, THREADS, smem_bytes>>>(
        E_S, W, pidx, part_W, part_b, v, c, ln_g, ln_b,
        proj_W, proj_b, out_g, out_b, out);
}